// round 1
// baseline (speedup 1.0000x reference)
#include <cuda_runtime.h>
#include <math.h>

#define TOKS 4096
#define HD   4096
#define ID   6400
#define NE   8

#define BM 128
#define BN 64
#define BK 16

// ---------------- device scratch (static; no runtime allocation) ----------------
__device__ int   g_cnt[NE];
__device__ int   g_off[NE];
__device__ int   g_tok[NE][TOKS];
__device__ float g_wt [NE][TOKS];
// packed per-expert rows of the SwiGLU intermediate; +BM rows padding so that
// partially-filled tiles can safely read past the live region.
__device__ float g_h[(size_t)(2 * TOKS + BM) * ID];

// ---------------- zero output + counters ----------------
__global__ void zero_kernel(float* __restrict__ out) {
    size_t n4 = (size_t)TOKS * HD / 4;
    float4 z = make_float4(0.f, 0.f, 0.f, 0.f);
    for (size_t k = (size_t)blockIdx.x * blockDim.x + threadIdx.x; k < n4;
         k += (size_t)gridDim.x * blockDim.x)
        ((float4*)out)[k] = z;
    if (blockIdx.x == 0 && threadIdx.x < NE) g_cnt[threadIdx.x] = 0;
}

// ---------------- router: logits -> softmax -> top2 -> renorm ----------------
__global__ void router_kernel(const float* __restrict__ x, const float* __restrict__ gw) {
    __shared__ float sx[HD];
    __shared__ float slog[NE];
    int t = blockIdx.x;
    const float* xr = x + (size_t)t * HD;
    for (int k = threadIdx.x; k < HD / 4; k += blockDim.x)
        ((float4*)sx)[k] = ((const float4*)xr)[k];
    __syncthreads();
    int warp = threadIdx.x >> 5, lane = threadIdx.x & 31;
    float s = 0.f;
    const float* g = gw + (size_t)warp * HD;
    for (int k = lane; k < HD; k += 32) s += sx[k] * g[k];
    #pragma unroll
    for (int o = 16; o; o >>= 1) s += __shfl_xor_sync(0xffffffffu, s, o);
    if (lane == 0) slog[warp] = s;
    __syncthreads();
    if (threadIdx.x == 0) {
        int i1 = 0;
        #pragma unroll
        for (int e = 1; e < NE; ++e) if (slog[e] > slog[i1]) i1 = e;
        int i2 = (i1 == 0) ? 1 : 0;
        #pragma unroll
        for (int e = 0; e < NE; ++e) if (e != i1 && slog[e] > slog[i2]) i2 = e;
        // renormalized top-2 softmax == 2-way softmax over the top-2 logits
        float p1 = 1.f / (1.f + expf(slog[i2] - slog[i1]));  // l1 >= l2, stable
        float p2 = 1.f - p1;
        int s1 = atomicAdd(&g_cnt[i1], 1);
        g_tok[i1][s1] = t; g_wt[i1][s1] = p1;
        int s2 = atomicAdd(&g_cnt[i2], 1);
        g_tok[i2][s2] = t; g_wt[i2][s2] = p2;
    }
}

__global__ void offsets_kernel() {
    int o = 0;
    for (int e = 0; e < NE; ++e) { g_off[e] = o; o += g_cnt[e]; }
}

// ---------------- GEMM1: h = silu(x@w1^T) * (x@w3^T), gathered rows ----------------
__global__ void __launch_bounds__(256, 2) gemm1_kernel(const float* __restrict__ x,
                                                       const float* __restrict__ w1,
                                                       const float* __restrict__ w3) {
    int e = blockIdx.z;
    int cnt = g_cnt[e];
    int m0 = blockIdx.x * BM;
    if (m0 >= cnt) return;                       // fixed grid, data-dependent early exit
    int n0 = blockIdx.y * BN;

    __shared__ float As[BM][BK + 1];
    __shared__ float Bg[BN][BK + 1];
    __shared__ float Bu[BN][BK + 1];
    __shared__ int   stok[BM];

    int tid = threadIdx.x;
    if (tid < BM) {
        int s = m0 + tid;
        stok[tid] = (s < cnt) ? g_tok[e][s] : 0;  // clamp to a valid row
    }
    __syncthreads();

    const float* w1e = w1 + (size_t)e * ID * HD;
    const float* w3e = w3 + (size_t)e * ID * HD;

    float accg[8][4], accu[8][4];
    #pragma unroll
    for (int i = 0; i < 8; ++i)
        #pragma unroll
        for (int j = 0; j < 4; ++j) { accg[i][j] = 0.f; accu[i][j] = 0.f; }

    int ty = tid >> 4, tx = tid & 15;
    int arow = tid >> 1, akc = (tid & 1) * 8;    // each thread: 8 floats of one A row
    int brow = tid >> 2, bkc = (tid & 3) * 4;    // each thread: 4 floats of one B row

    for (int k0 = 0; k0 < HD; k0 += BK) {
        const float* ap = x + (size_t)stok[arow] * HD + k0 + akc;
        float4 a0 = *(const float4*)ap;
        float4 a1 = *(const float4*)(ap + 4);
        As[arow][akc + 0] = a0.x; As[arow][akc + 1] = a0.y;
        As[arow][akc + 2] = a0.z; As[arow][akc + 3] = a0.w;
        As[arow][akc + 4] = a1.x; As[arow][akc + 5] = a1.y;
        As[arow][akc + 6] = a1.z; As[arow][akc + 7] = a1.w;

        size_t bo = (size_t)(n0 + brow) * HD + k0 + bkc;
        float4 vg = *(const float4*)(w1e + bo);
        float4 vu = *(const float4*)(w3e + bo);
        Bg[brow][bkc + 0] = vg.x; Bg[brow][bkc + 1] = vg.y;
        Bg[brow][bkc + 2] = vg.z; Bg[brow][bkc + 3] = vg.w;
        Bu[brow][bkc + 0] = vu.x; Bu[brow][bkc + 1] = vu.y;
        Bu[brow][bkc + 2] = vu.z; Bu[brow][bkc + 3] = vu.w;
        __syncthreads();

        #pragma unroll
        for (int kk = 0; kk < BK; ++kk) {
            float a[8], bg[4], bu[4];
            #pragma unroll
            for (int i = 0; i < 8; ++i) a[i] = As[ty * 8 + i][kk];
            #pragma unroll
            for (int j = 0; j < 4; ++j) { bg[j] = Bg[tx * 4 + j][kk]; bu[j] = Bu[tx * 4 + j][kk]; }
            #pragma unroll
            for (int i = 0; i < 8; ++i)
                #pragma unroll
                for (int j = 0; j < 4; ++j) {
                    accg[i][j] += a[i] * bg[j];
                    accu[i][j] += a[i] * bu[j];
                }
        }
        __syncthreads();
    }

    int base = g_off[e] + m0;
    #pragma unroll
    for (int i = 0; i < 8; ++i) {
        int s = ty * 8 + i;
        if (m0 + s < cnt) {
            float* hp = g_h + (size_t)(base + s) * ID + n0 + tx * 4;
            #pragma unroll
            for (int j = 0; j < 4; ++j) {
                float gv = accg[i][j];
                hp[j] = (gv / (1.f + __expf(-gv))) * accu[i][j];
            }
        }
    }
}

// ---------------- GEMM2: out[tok] += wt * (h @ w2^T), scattered ----------------
__global__ void __launch_bounds__(256, 2) gemm2_kernel(const float* __restrict__ w2,
                                                       float* __restrict__ out) {
    int e = blockIdx.z;
    int cnt = g_cnt[e];
    int m0 = blockIdx.x * BM;
    if (m0 >= cnt) return;
    int n0 = blockIdx.y * BN;

    __shared__ float As[BM][BK + 1];
    __shared__ float Bs[BN][BK + 1];
    __shared__ int   stok[BM];
    __shared__ float swt[BM];

    int tid = threadIdx.x;
    if (tid < BM) {
        int s = m0 + tid;
        stok[tid] = (s < cnt) ? g_tok[e][s] : 0;
        swt[tid]  = (s < cnt) ? g_wt[e][s] : 0.f;
    }
    __syncthreads();

    const float* hbase = g_h + (size_t)(g_off[e] + m0) * ID;
    const float* w2e   = w2 + (size_t)e * HD * ID;

    float acc[8][4];
    #pragma unroll
    for (int i = 0; i < 8; ++i)
        #pragma unroll
        for (int j = 0; j < 4; ++j) acc[i][j] = 0.f;

    int ty = tid >> 4, tx = tid & 15;
    int arow = tid >> 1, akc = (tid & 1) * 8;
    int brow = tid >> 2, bkc = (tid & 3) * 4;

    for (int k0 = 0; k0 < ID; k0 += BK) {
        const float* ap = hbase + (size_t)arow * ID + k0 + akc;
        float4 a0 = *(const float4*)ap;
        float4 a1 = *(const float4*)(ap + 4);
        As[arow][akc + 0] = a0.x; As[arow][akc + 1] = a0.y;
        As[arow][akc + 2] = a0.z; As[arow][akc + 3] = a0.w;
        As[arow][akc + 4] = a1.x; As[arow][akc + 5] = a1.y;
        As[arow][akc + 6] = a1.z; As[arow][akc + 7] = a1.w;

        const float* bp = w2e + (size_t)(n0 + brow) * ID + k0 + bkc;
        float4 vb = *(const float4*)bp;
        Bs[brow][bkc + 0] = vb.x; Bs[brow][bkc + 1] = vb.y;
        Bs[brow][bkc + 2] = vb.z; Bs[brow][bkc + 3] = vb.w;
        __syncthreads();

        #pragma unroll
        for (int kk = 0; kk < BK; ++kk) {
            float a[8], b[4];
            #pragma unroll
            for (int i = 0; i < 8; ++i) a[i] = As[ty * 8 + i][kk];
            #pragma unroll
            for (int j = 0; j < 4; ++j) b[j] = Bs[tx * 4 + j][kk];
            #pragma unroll
            for (int i = 0; i < 8; ++i)
                #pragma unroll
                for (int j = 0; j < 4; ++j) acc[i][j] += a[i] * b[j];
        }
        __syncthreads();
    }

    #pragma unroll
    for (int i = 0; i < 8; ++i) {
        int s = ty * 8 + i;
        if (m0 + s < cnt) {
            float w = swt[s];
            float* op = out + (size_t)stok[s] * HD + n0 + tx * 4;
            #pragma unroll
            for (int j = 0; j < 4; ++j)
                atomicAdd(op + j, w * acc[i][j]);   // exactly 2 adds/elem -> deterministic
        }
    }
}

// ---------------- launch ----------------
extern "C" void kernel_launch(void* const* d_in, const int* in_sizes, int n_in,
                              void* d_out, int out_size) {
    const float* x  = (const float*)d_in[0];
    const float* gw = (const float*)d_in[1];
    const float* w1 = (const float*)d_in[2];
    const float* w3 = (const float*)d_in[3];
    const float* w2 = (const float*)d_in[4];
    float* out = (float*)d_out;

    zero_kernel<<<2048, 256>>>(out);
    router_kernel<<<TOKS, 256>>>(x, gw);
    offsets_kernel<<<1, 1>>>();
    gemm1_kernel<<<dim3(TOKS / BM, ID / BN, NE), 256>>>(x, w1, w3);
    gemm2_kernel<<<dim3(TOKS / BM, HD / BN, NE), 256>>>(w2, out);
}

// round 3
// speedup vs baseline: 2.7465x; 2.7465x over previous
#include <cuda_runtime.h>
#include <math.h>

#define TOKS 4096
#define HD   4096
#define ID   6400
#define NE   8

// ---------------- device scratch (static; no runtime allocation) ----------------
__device__ int   g_cnt[NE];
__device__ int   g_off[NE];
__device__ int   g_tok[NE][TOKS];
__device__ float g_wt [NE][TOKS];
__device__ float g_h[(size_t)(2 * TOKS + 128) * ID];

// ---------------- helpers ----------------
__device__ __forceinline__ unsigned su(const void* p) {
    return (unsigned)__cvta_generic_to_shared(p);
}
__device__ __forceinline__ void cpasync16(unsigned dst, const void* src) {
    asm volatile("cp.async.cg.shared.global [%0], [%1], 16;\n" ::"r"(dst), "l"(src));
}
__device__ __forceinline__ void cp_commit() { asm volatile("cp.async.commit_group;\n"); }
__device__ __forceinline__ void cp_wait0()  { asm volatile("cp.async.wait_group 0;\n"); }

__device__ __forceinline__ unsigned f2tf(float v) {
    unsigned r;
    asm("cvt.rna.tf32.f32 %0, %1;\n" : "=r"(r) : "f"(v));
    return r;
}
// split fp32 into tf32 hi + fp32 residual lo (lo truncated by HW; 2nd-order err)
__device__ __forceinline__ void split(float v, unsigned& hi, unsigned& lo) {
    hi = f2tf(v);
    lo = __float_as_uint(v - __uint_as_float(hi));
}

__device__ __forceinline__ void mma8(float* c, const unsigned* a, unsigned b0, unsigned b1) {
    asm volatile(
        "mma.sync.aligned.m16n8k8.row.col.f32.tf32.tf32.f32 "
        "{%0,%1,%2,%3},{%4,%5,%6,%7},{%8,%9},{%0,%1,%2,%3};\n"
        : "+f"(c[0]), "+f"(c[1]), "+f"(c[2]), "+f"(c[3])
        : "r"(a[0]), "r"(a[1]), "r"(a[2]), "r"(a[3]), "r"(b0), "r"(b1));
}
// 3xTF32: acc += a*b with ~fp32 precision
__device__ __forceinline__ void mma3(float* c, const unsigned* ah, const unsigned* al,
                                     unsigned bh0, unsigned bh1, unsigned bl0, unsigned bl1) {
    mma8(c, al, bh0, bh1);
    mma8(c, ah, bl0, bl1);
    mma8(c, ah, bh0, bh1);
}

// ---------------- zero output + counters ----------------
__global__ void zero_kernel(float* __restrict__ out) {
    size_t n4 = (size_t)TOKS * HD / 4;
    float4 z = make_float4(0.f, 0.f, 0.f, 0.f);
    for (size_t k = (size_t)blockIdx.x * blockDim.x + threadIdx.x; k < n4;
         k += (size_t)gridDim.x * blockDim.x)
        ((float4*)out)[k] = z;
    if (blockIdx.x == 0 && threadIdx.x < NE) g_cnt[threadIdx.x] = 0;
}

// ---------------- router ----------------
__global__ void router_kernel(const float* __restrict__ x, const float* __restrict__ gw) {
    __shared__ float sx[HD];
    __shared__ float slog[NE];
    int t = blockIdx.x;
    const float* xr = x + (size_t)t * HD;
    for (int k = threadIdx.x; k < HD / 4; k += blockDim.x)
        ((float4*)sx)[k] = ((const float4*)xr)[k];
    __syncthreads();
    int warp = threadIdx.x >> 5, lane = threadIdx.x & 31;
    float s = 0.f;
    const float* g = gw + (size_t)warp * HD;
    for (int k = lane; k < HD; k += 32) s += sx[k] * g[k];
    #pragma unroll
    for (int o = 16; o; o >>= 1) s += __shfl_xor_sync(0xffffffffu, s, o);
    if (lane == 0) slog[warp] = s;
    __syncthreads();
    if (threadIdx.x == 0) {
        int i1 = 0;
        #pragma unroll
        for (int e = 1; e < NE; ++e) if (slog[e] > slog[i1]) i1 = e;
        int i2 = (i1 == 0) ? 1 : 0;
        #pragma unroll
        for (int e = 0; e < NE; ++e) if (e != i1 && slog[e] > slog[i2]) i2 = e;
        float p1 = 1.f / (1.f + expf(slog[i2] - slog[i1]));
        float p2 = 1.f - p1;
        int s1 = atomicAdd(&g_cnt[i1], 1);
        g_tok[i1][s1] = t; g_wt[i1][s1] = p1;
        int s2 = atomicAdd(&g_cnt[i2], 1);
        g_tok[i2][s2] = t; g_wt[i2][s2] = p2;
    }
}

__global__ void offsets_kernel() {
    int o = 0;
    for (int e = 0; e < NE; ++e) { g_off[e] = o; o += g_cnt[e]; }
}

// =================================================================
// GEMM1: h = silu(x@w1^T) * (x@w3^T)   tile 128x64, dual-B, 3xtf32
// =================================================================
__global__ void __launch_bounds__(256, 1) gemm1_kernel(const float* __restrict__ x,
                                                       const float* __restrict__ w1,
                                                       const float* __restrict__ w3) {
    int e = blockIdx.z;
    int cnt = g_cnt[e];
    int m0 = blockIdx.x * 128;
    if (m0 >= cnt) return;
    int n0 = blockIdx.y * 64;

    extern __shared__ float sm[];
    float* As = sm;            // [2][128*36]
    float* Bg = sm + 9216;     // [2][64*36]
    float* Bu = sm + 13824;
    int* stok = (int*)(sm + 18432);

    int tid = threadIdx.x;
    if (tid < 128) {
        int s = m0 + tid;
        stok[tid] = (s < cnt) ? g_tok[e][s] : 0;
    }
    __syncthreads();

    const float* w1e = w1 + (size_t)e * ID * HD;
    const float* w3e = w3 + (size_t)e * ID * HD;

    int warp = tid >> 5, lane = tid & 31, g = lane >> 2, t = lane & 3;
    int wm = (warp & 3) * 32, wn = (warp >> 2) * 32;

    float accg[2][4][4], accu[2][4][4];
    #pragma unroll
    for (int i = 0; i < 2; ++i)
        #pragma unroll
        for (int j = 0; j < 4; ++j)
            #pragma unroll
            for (int k = 0; k < 4; ++k) { accg[i][j][k] = 0.f; accu[i][j][k] = 0.f; }

    const int NK = HD / 32;            // 128

    auto load_stage = [&](int st, int k0) {
        float* Ad = As + st * 4608;
        #pragma unroll
        for (int p = 0; p < 4; ++p) {
            int c = tid + p * 256;
            int r = c >> 3, kc = (c & 7) * 4;
            cpasync16(su(Ad + r * 36 + kc), x + (size_t)stok[r] * HD + k0 + kc);
        }
        float* Bgd = Bg + st * 2304;
        float* Bud = Bu + st * 2304;
        #pragma unroll
        for (int p = 0; p < 2; ++p) {
            int c = tid + p * 256;
            int r = c >> 3, kc = (c & 7) * 4;
            size_t off = (size_t)(n0 + r) * HD + k0 + kc;
            cpasync16(su(Bgd + r * 36 + kc), w1e + off);
            cpasync16(su(Bud + r * 36 + kc), w3e + off);
        }
    };

    load_stage(0, 0);
    cp_commit();

    for (int it = 0; it < NK; ++it) {
        cp_wait0();
        __syncthreads();
        if (it + 1 < NK) { load_stage((it + 1) & 1, (it + 1) * 32); cp_commit(); }

        const float* Ab  = As + (it & 1) * 4608;
        const float* Bgb = Bg + (it & 1) * 2304;
        const float* Bub = Bu + (it & 1) * 2304;

        #pragma unroll
        for (int kk = 0; kk < 4; ++kk) {
            int k = kk * 8;
            unsigned ah[2][4], al[2][4];
            #pragma unroll
            for (int mt = 0; mt < 2; ++mt) {
                const float* ap = Ab + (wm + mt * 16 + g) * 36 + k + t;
                split(ap[0],          ah[mt][0], al[mt][0]);
                split(ap[8 * 36],     ah[mt][1], al[mt][1]);
                split(ap[4],          ah[mt][2], al[mt][2]);
                split(ap[8 * 36 + 4], ah[mt][3], al[mt][3]);
            }
            #pragma unroll
            for (int nt = 0; nt < 4; ++nt) {
                const float* bgp = Bgb + (wn + nt * 8 + g) * 36 + k + t;
                unsigned bgh0, bgl0, bgh1, bgl1;
                split(bgp[0], bgh0, bgl0);
                split(bgp[4], bgh1, bgl1);
                const float* bup = Bub + (wn + nt * 8 + g) * 36 + k + t;
                unsigned buh0, bul0, buh1, bul1;
                split(bup[0], buh0, bul0);
                split(bup[4], buh1, bul1);
                #pragma unroll
                for (int mt = 0; mt < 2; ++mt) {
                    mma3(accg[mt][nt], ah[mt], al[mt], bgh0, bgh1, bgl0, bgl1);
                    mma3(accu[mt][nt], ah[mt], al[mt], buh0, buh1, bul0, bul1);
                }
            }
        }
    }

    int base = g_off[e] + m0;
    #pragma unroll
    for (int mt = 0; mt < 2; ++mt) {
        #pragma unroll
        for (int half = 0; half < 2; ++half) {
            int ml = wm + mt * 16 + g + half * 8;
            if (m0 + ml < cnt) {
                float* hp = g_h + (size_t)(base + ml) * ID + n0 + wn;
                #pragma unroll
                for (int nt = 0; nt < 4; ++nt) {
                    float gv0 = accg[mt][nt][half * 2], gv1 = accg[mt][nt][half * 2 + 1];
                    float uv0 = accu[mt][nt][half * 2], uv1 = accu[mt][nt][half * 2 + 1];
                    float2 o;
                    o.x = gv0 / (1.f + __expf(-gv0)) * uv0;
                    o.y = gv1 / (1.f + __expf(-gv1)) * uv1;
                    *(float2*)(hp + nt * 8 + t * 2) = o;
                }
            }
        }
    }
}

// =================================================================
// GEMM2: out[tok] += wt * (h @ w2^T)   tile 128x128, 3xtf32
// =================================================================
__global__ void __launch_bounds__(256, 1) gemm2_kernel(const float* __restrict__ w2,
                                                       float* __restrict__ out) {
    int e = blockIdx.z;
    int cnt = g_cnt[e];
    int m0 = blockIdx.x * 128;
    if (m0 >= cnt) return;
    int n0 = blockIdx.y * 128;

    extern __shared__ float sm[];
    float* As = sm;            // [2][128*36]
    float* Bs = sm + 9216;     // [2][128*36]
    int*   stok = (int*)(sm + 18432);
    float* swt  = (float*)(stok + 128);

    int tid = threadIdx.x;
    if (tid < 128) {
        int s = m0 + tid;
        stok[tid] = (s < cnt) ? g_tok[e][s] : 0;
        swt[tid]  = (s < cnt) ? g_wt[e][s] : 0.f;
    }
    __syncthreads();

    const float* hbase = g_h + (size_t)(g_off[e] + m0) * ID;
    const float* w2e   = w2 + (size_t)e * HD * ID;

    int warp = tid >> 5, lane = tid & 31, g = lane >> 2, t = lane & 3;
    int wm = (warp & 1) * 64, wn = (warp >> 1) * 32;

    float acc[4][4][4];
    #pragma unroll
    for (int i = 0; i < 4; ++i)
        #pragma unroll
        for (int j = 0; j < 4; ++j)
            #pragma unroll
            for (int k = 0; k < 4; ++k) acc[i][j][k] = 0.f;

    const int NK = ID / 32;            // 200

    auto load_stage = [&](int st, int k0) {
        float* Ad = As + st * 4608;
        float* Bd = Bs + st * 4608;
        #pragma unroll
        for (int p = 0; p < 4; ++p) {
            int c = tid + p * 256;
            int r = c >> 3, kc = (c & 7) * 4;
            cpasync16(su(Ad + r * 36 + kc), hbase + (size_t)r * ID + k0 + kc);
            cpasync16(su(Bd + r * 36 + kc), w2e + (size_t)(n0 + r) * ID + k0 + kc);
        }
    };

    load_stage(0, 0);
    cp_commit();

    for (int it = 0; it < NK; ++it) {
        cp_wait0();
        __syncthreads();
        if (it + 1 < NK) { load_stage((it + 1) & 1, (it + 1) * 32); cp_commit(); }

        const float* Ab = As + (it & 1) * 4608;
        const float* Bb = Bs + (it & 1) * 4608;

        #pragma unroll
        for (int kk = 0; kk < 4; ++kk) {
            int k = kk * 8;
            unsigned ah[4][4], al[4][4];
            #pragma unroll
            for (int mt = 0; mt < 4; ++mt) {
                const float* ap = Ab + (wm + mt * 16 + g) * 36 + k + t;
                split(ap[0],          ah[mt][0], al[mt][0]);
                split(ap[8 * 36],     ah[mt][1], al[mt][1]);
                split(ap[4],          ah[mt][2], al[mt][2]);
                split(ap[8 * 36 + 4], ah[mt][3], al[mt][3]);
            }
            #pragma unroll
            for (int nt = 0; nt < 4; ++nt) {
                const float* bp = Bb + (wn + nt * 8 + g) * 36 + k + t;
                unsigned bh0, bl0, bh1, bl1;
                split(bp[0], bh0, bl0);
                split(bp[4], bh1, bl1);
                #pragma unroll
                for (int mt = 0; mt < 4; ++mt)
                    mma3(acc[mt][nt], ah[mt], al[mt], bh0, bh1, bl0, bl1);
            }
        }
    }

    #pragma unroll
    for (int mt = 0; mt < 4; ++mt) {
        #pragma unroll
        for (int half = 0; half < 2; ++half) {
            int ml = wm + mt * 16 + g + half * 8;
            if (m0 + ml < cnt) {
                float w = swt[ml];
                float* op = out + (size_t)stok[ml] * HD + n0 + wn;
                #pragma unroll
                for (int nt = 0; nt < 4; ++nt) {
                    atomicAdd(op + nt * 8 + t * 2,     w * acc[mt][nt][half * 2]);
                    atomicAdd(op + nt * 8 + t * 2 + 1, w * acc[mt][nt][half * 2 + 1]);
                }
            }
        }
    }
}

// ---------------- launch ----------------
extern "C" void kernel_launch(void* const* d_in, const int* in_sizes, int n_in,
                              void* d_out, int out_size) {
    const float* x  = (const float*)d_in[0];
    const float* gw = (const float*)d_in[1];
    const float* w1 = (const float*)d_in[2];
    const float* w3 = (const float*)d_in[3];
    const float* w2 = (const float*)d_in[4];
    float* out = (float*)d_out;

    cudaFuncSetAttribute(gemm1_kernel, cudaFuncAttributeMaxDynamicSharedMemorySize, 74240);
    cudaFuncSetAttribute(gemm2_kernel, cudaFuncAttributeMaxDynamicSharedMemorySize, 74752);

    zero_kernel<<<2048, 256>>>(out);
    router_kernel<<<TOKS, 256>>>(x, gw);
    offsets_kernel<<<1, 1>>>();
    gemm1_kernel<<<dim3(TOKS / 128, ID / 64, NE), 256, 74240>>>(x, w1, w3);
    gemm2_kernel<<<dim3(TOKS / 128, HD / 128, NE), 256, 74752>>>(w2, out);
}

// round 4
// speedup vs baseline: 3.3195x; 1.2086x over previous
#include <cuda_runtime.h>
#include <cuda_bf16.h>
#include <math.h>

#define TOKS 4096
#define HD   4096
#define ID   6400
#define NE   8
#define SZW  ((size_t)NE * ID * HD)
#define SZX  ((size_t)TOKS * HD)
#define HSLOT (2 * TOKS + 128)
#define SZH  ((size_t)HSLOT * ID)
#define STR  40   // smem row stride in halves (80B) - conflict-free for frag LDS.32

// ---------------- device scratch (static; no runtime allocation) ----------------
__device__ int   g_cnt[NE];
__device__ int   g_off[NE];
__device__ int   g_tok[NE][TOKS];
__device__ float g_wt [NE][TOKS];
__device__ __nv_bfloat16 g_w1h[SZW], g_w1l[SZW];
__device__ __nv_bfloat16 g_w3h[SZW], g_w3l[SZW];
__device__ __nv_bfloat16 g_w2h[SZW], g_w2l[SZW];
__device__ __nv_bfloat16 g_xh[SZX],  g_xl[SZX];
__device__ __nv_bfloat16 g_hh[SZH],  g_hl[SZH];

// ---------------- helpers ----------------
__device__ __forceinline__ unsigned su(const void* p) {
    return (unsigned)__cvta_generic_to_shared(p);
}
__device__ __forceinline__ void cpasync16(unsigned dst, const void* src) {
    asm volatile("cp.async.cg.shared.global [%0], [%1], 16;\n" ::"r"(dst), "l"(src));
}
__device__ __forceinline__ void cp_commit() { asm volatile("cp.async.commit_group;\n"); }
__device__ __forceinline__ void cp_wait0()  { asm volatile("cp.async.wait_group 0;\n"); }

__device__ __forceinline__ void mmabf(float* c, const unsigned* a, unsigned b0, unsigned b1) {
    asm volatile(
        "mma.sync.aligned.m16n8k16.row.col.f32.bf16.bf16.f32 "
        "{%0,%1,%2,%3},{%4,%5,%6,%7},{%8,%9},{%0,%1,%2,%3};\n"
        : "+f"(c[0]), "+f"(c[1]), "+f"(c[2]), "+f"(c[3])
        : "r"(a[0]), "r"(a[1]), "r"(a[2]), "r"(a[3]), "r"(b0), "r"(b1));
}
// 3-term compensated bf16: acc += a*b  (al*bh + ah*bl + ah*bh)
__device__ __forceinline__ void mma3(float* c, const unsigned* ah, const unsigned* al,
                                     unsigned bh0, unsigned bh1, unsigned bl0, unsigned bl1) {
    mmabf(c, al, bh0, bh1);
    mmabf(c, ah, bl0, bl1);
    mmabf(c, ah, bh0, bh1);
}

__device__ __forceinline__ void split2(float a, float b, __nv_bfloat162& hi, __nv_bfloat162& lo) {
    __nv_bfloat16 ha = __float2bfloat16_rn(a);
    __nv_bfloat16 hb = __float2bfloat16_rn(b);
    hi = __halves2bfloat162(ha, hb);
    lo = __halves2bfloat162(__float2bfloat16_rn(a - __bfloat162float(ha)),
                            __float2bfloat16_rn(b - __bfloat162float(hb)));
}

// ---------------- operand split precompute ----------------
__global__ void split_kernel(const float* __restrict__ src, __nv_bfloat16* __restrict__ hi,
                             __nv_bfloat16* __restrict__ lo, size_t n4) {
    for (size_t i = (size_t)blockIdx.x * blockDim.x + threadIdx.x; i < n4;
         i += (size_t)gridDim.x * blockDim.x) {
        float4 v = ((const float4*)src)[i];
        __nv_bfloat162 h01, l01, h23, l23;
        split2(v.x, v.y, h01, l01);
        split2(v.z, v.w, h23, l23);
        ((__nv_bfloat162*)hi)[2 * i]     = h01;
        ((__nv_bfloat162*)hi)[2 * i + 1] = h23;
        ((__nv_bfloat162*)lo)[2 * i]     = l01;
        ((__nv_bfloat162*)lo)[2 * i + 1] = l23;
    }
}

// ---------------- zero output + counters ----------------
__global__ void zero_kernel(float* __restrict__ out) {
    size_t n4 = (size_t)TOKS * HD / 4;
    float4 z = make_float4(0.f, 0.f, 0.f, 0.f);
    for (size_t k = (size_t)blockIdx.x * blockDim.x + threadIdx.x; k < n4;
         k += (size_t)gridDim.x * blockDim.x)
        ((float4*)out)[k] = z;
    if (blockIdx.x == 0 && threadIdx.x < NE) g_cnt[threadIdx.x] = 0;
}

// ---------------- router ----------------
__global__ void router_kernel(const float* __restrict__ x, const float* __restrict__ gw) {
    __shared__ float sx[HD];
    __shared__ float slog[NE];
    int t = blockIdx.x;
    const float* xr = x + (size_t)t * HD;
    for (int k = threadIdx.x; k < HD / 4; k += blockDim.x)
        ((float4*)sx)[k] = ((const float4*)xr)[k];
    __syncthreads();
    int warp = threadIdx.x >> 5, lane = threadIdx.x & 31;
    float s = 0.f;
    const float* g = gw + (size_t)warp * HD;
    for (int k = lane; k < HD; k += 32) s += sx[k] * g[k];
    #pragma unroll
    for (int o = 16; o; o >>= 1) s += __shfl_xor_sync(0xffffffffu, s, o);
    if (lane == 0) slog[warp] = s;
    __syncthreads();
    if (threadIdx.x == 0) {
        int i1 = 0;
        #pragma unroll
        for (int e = 1; e < NE; ++e) if (slog[e] > slog[i1]) i1 = e;
        int i2 = (i1 == 0) ? 1 : 0;
        #pragma unroll
        for (int e = 0; e < NE; ++e) if (e != i1 && slog[e] > slog[i2]) i2 = e;
        float p1 = 1.f / (1.f + expf(slog[i2] - slog[i1]));
        float p2 = 1.f - p1;
        int s1 = atomicAdd(&g_cnt[i1], 1);
        g_tok[i1][s1] = t; g_wt[i1][s1] = p1;
        int s2 = atomicAdd(&g_cnt[i2], 1);
        g_tok[i2][s2] = t; g_wt[i2][s2] = p2;
    }
}

__global__ void offsets_kernel() {
    int o = 0;
    for (int e = 0; e < NE; ++e) { g_off[e] = o; o += g_cnt[e]; }
}

// =================================================================
// GEMM1: h = silu(x@w1^T) * (x@w3^T)  tile 128x64, BK=32, 3xbf16
// smem halves: Ah[2][5120] Al[2][5120] Bgh/Bgl/Buh/Bul[2][2560] = 40960
// bytes = 81920 + 512(stok) = 82432
// =================================================================
__global__ void __launch_bounds__(256, 2) gemm1_kernel() {
    int e = blockIdx.z;
    int cnt = g_cnt[e];
    int m0 = blockIdx.x * 128;
    if (m0 >= cnt) return;
    int n0 = blockIdx.y * 64;

    extern __shared__ __nv_bfloat16 sm[];
    __nv_bfloat16* Ah  = sm;
    __nv_bfloat16* Al  = sm + 10240;
    __nv_bfloat16* Bgh = sm + 20480;
    __nv_bfloat16* Bgl = sm + 25600;
    __nv_bfloat16* Buh = sm + 30720;
    __nv_bfloat16* Bul = sm + 35840;
    int* stok = (int*)(sm + 40960);

    int tid = threadIdx.x;
    if (tid < 128) {
        int s = m0 + tid;
        stok[tid] = (s < cnt) ? g_tok[e][s] : 0;
    }
    __syncthreads();

    const __nv_bfloat16* w1h = g_w1h + (size_t)e * ID * HD;
    const __nv_bfloat16* w1l = g_w1l + (size_t)e * ID * HD;
    const __nv_bfloat16* w3h = g_w3h + (size_t)e * ID * HD;
    const __nv_bfloat16* w3l = g_w3l + (size_t)e * ID * HD;

    int warp = tid >> 5, lane = tid & 31, g = lane >> 2, t = lane & 3;
    int wm = (warp & 3) * 32, wn = (warp >> 2) * 32;

    float accg[2][4][4], accu[2][4][4];
    #pragma unroll
    for (int i = 0; i < 2; ++i)
        #pragma unroll
        for (int j = 0; j < 4; ++j)
            #pragma unroll
            for (int k = 0; k < 4; ++k) { accg[i][j][k] = 0.f; accu[i][j][k] = 0.f; }

    const int NK = HD / 32;  // 128

    auto load_stage = [&](int st, int k0) {
        #pragma unroll
        for (int p = 0; p < 4; ++p) {
            int c = tid + p * 256;                 // 0..1023 : A hi then A lo
            int r = (c & 511) >> 2, kc = (c & 3) * 8;
            const __nv_bfloat16* src = ((c >> 9) ? g_xl : g_xh) + (size_t)stok[r] * HD + k0 + kc;
            __nv_bfloat16* dst = ((c >> 9) ? Al : Ah) + st * 5120 + r * STR + kc;
            cpasync16(su(dst), src);
        }
        int r = tid >> 2, kc = (tid & 3) * 8;
        size_t off = (size_t)(n0 + r) * HD + k0 + kc;
        int d = st * 2560 + r * STR + kc;
        cpasync16(su(Bgh + d), w1h + off);
        cpasync16(su(Bgl + d), w1l + off);
        cpasync16(su(Buh + d), w3h + off);
        cpasync16(su(Bul + d), w3l + off);
    };

    load_stage(0, 0);
    cp_commit();

    for (int it = 0; it < NK; ++it) {
        cp_wait0();
        __syncthreads();
        if (it + 1 < NK) { load_stage((it + 1) & 1, (it + 1) * 32); cp_commit(); }

        const __nv_bfloat16* Ahb  = Ah  + (it & 1) * 5120;
        const __nv_bfloat16* Alb  = Al  + (it & 1) * 5120;
        const __nv_bfloat16* Bghb = Bgh + (it & 1) * 2560;
        const __nv_bfloat16* Bglb = Bgl + (it & 1) * 2560;
        const __nv_bfloat16* Buhb = Buh + (it & 1) * 2560;
        const __nv_bfloat16* Bulb = Bul + (it & 1) * 2560;

        #pragma unroll
        for (int kk = 0; kk < 2; ++kk) {
            int k = kk * 16;
            unsigned ah[2][4], al[2][4];
            #pragma unroll
            for (int mt = 0; mt < 2; ++mt) {
                int off = (wm + mt * 16 + g) * STR + k + 2 * t;
                ah[mt][0] = *(const unsigned*)(Ahb + off);
                ah[mt][1] = *(const unsigned*)(Ahb + off + 8 * STR);
                ah[mt][2] = *(const unsigned*)(Ahb + off + 8);
                ah[mt][3] = *(const unsigned*)(Ahb + off + 8 * STR + 8);
                al[mt][0] = *(const unsigned*)(Alb + off);
                al[mt][1] = *(const unsigned*)(Alb + off + 8 * STR);
                al[mt][2] = *(const unsigned*)(Alb + off + 8);
                al[mt][3] = *(const unsigned*)(Alb + off + 8 * STR + 8);
            }
            #pragma unroll
            for (int nt = 0; nt < 4; ++nt) {
                int off = (wn + nt * 8 + g) * STR + k + 2 * t;
                unsigned bgh0 = *(const unsigned*)(Bghb + off), bgh1 = *(const unsigned*)(Bghb + off + 8);
                unsigned bgl0 = *(const unsigned*)(Bglb + off), bgl1 = *(const unsigned*)(Bglb + off + 8);
                unsigned buh0 = *(const unsigned*)(Buhb + off), buh1 = *(const unsigned*)(Buhb + off + 8);
                unsigned bul0 = *(const unsigned*)(Bulb + off), bul1 = *(const unsigned*)(Bulb + off + 8);
                #pragma unroll
                for (int mt = 0; mt < 2; ++mt) {
                    mma3(accg[mt][nt], ah[mt], al[mt], bgh0, bgh1, bgl0, bgl1);
                    mma3(accu[mt][nt], ah[mt], al[mt], buh0, buh1, bul0, bul1);
                }
            }
        }
    }

    int base = g_off[e] + m0;
    #pragma unroll
    for (int mt = 0; mt < 2; ++mt) {
        #pragma unroll
        for (int half = 0; half < 2; ++half) {
            int ml = wm + mt * 16 + g + half * 8;
            if (m0 + ml < cnt) {
                size_t ro = (size_t)(base + ml) * ID + n0 + wn;
                #pragma unroll
                for (int nt = 0; nt < 4; ++nt) {
                    float gv0 = accg[mt][nt][half * 2], gv1 = accg[mt][nt][half * 2 + 1];
                    float uv0 = accu[mt][nt][half * 2], uv1 = accu[mt][nt][half * 2 + 1];
                    float h0 = gv0 / (1.f + __expf(-gv0)) * uv0;
                    float h1 = gv1 / (1.f + __expf(-gv1)) * uv1;
                    __nv_bfloat162 hi, lo;
                    split2(h0, h1, hi, lo);
                    *(__nv_bfloat162*)(g_hh + ro + nt * 8 + 2 * t) = hi;
                    *(__nv_bfloat162*)(g_hl + ro + nt * 8 + 2 * t) = lo;
                }
            }
        }
    }
}

// =================================================================
// GEMM2: out[tok] += wt * (h @ w2^T)  tile 128x128, BK=32, 3xbf16
// smem halves: Ah/Al/Bh/Bl [2][5120] = 40960 -> 81920B + 1024 = 82944
// =================================================================
__global__ void __launch_bounds__(256, 2) gemm2_kernel(float* __restrict__ out) {
    int e = blockIdx.z;
    int cnt = g_cnt[e];
    int m0 = blockIdx.x * 128;
    if (m0 >= cnt) return;
    int n0 = blockIdx.y * 128;

    extern __shared__ __nv_bfloat16 sm[];
    __nv_bfloat16* Ah = sm;
    __nv_bfloat16* Al = sm + 10240;
    __nv_bfloat16* Bh = sm + 20480;
    __nv_bfloat16* Bl = sm + 30720;
    int*   stok = (int*)(sm + 40960);
    float* swt  = (float*)(stok + 128);

    int tid = threadIdx.x;
    if (tid < 128) {
        int s = m0 + tid;
        stok[tid] = (s < cnt) ? g_tok[e][s] : 0;
        swt[tid]  = (s < cnt) ? g_wt[e][s] : 0.f;
    }
    __syncthreads();

    size_t hbase = (size_t)(g_off[e] + m0) * ID;
    const __nv_bfloat16* w2h = g_w2h + (size_t)e * HD * ID;
    const __nv_bfloat16* w2l = g_w2l + (size_t)e * HD * ID;

    int warp = tid >> 5, lane = tid & 31, g = lane >> 2, t = lane & 3;
    int wm = (warp & 1) * 64, wn = (warp >> 1) * 32;

    float acc[4][4][4];
    #pragma unroll
    for (int i = 0; i < 4; ++i)
        #pragma unroll
        for (int j = 0; j < 4; ++j)
            #pragma unroll
            for (int k = 0; k < 4; ++k) acc[i][j][k] = 0.f;

    const int NK = ID / 32;  // 200

    auto load_stage = [&](int st, int k0) {
        #pragma unroll
        for (int p = 0; p < 4; ++p) {
            int c = tid + p * 256;                 // A hi (512) then A lo (512)
            int r = (c & 511) >> 2, kc = (c & 3) * 8;
            const __nv_bfloat16* src = ((c >> 9) ? g_hl : g_hh) + hbase + (size_t)r * ID + k0 + kc;
            __nv_bfloat16* dst = ((c >> 9) ? Al : Ah) + st * 5120 + r * STR + kc;
            cpasync16(su(dst), src);
        }
        #pragma unroll
        for (int p = 0; p < 4; ++p) {
            int c = tid + p * 256;                 // B hi (512) then B lo (512)
            int r = (c & 511) >> 2, kc = (c & 3) * 8;
            const __nv_bfloat16* src = ((c >> 9) ? w2l : w2h) + (size_t)(n0 + r) * ID + k0 + kc;
            __nv_bfloat16* dst = ((c >> 9) ? Bl : Bh) + st * 5120 + r * STR + kc;
            cpasync16(su(dst), src);
        }
    };

    load_stage(0, 0);
    cp_commit();

    for (int it = 0; it < NK; ++it) {
        cp_wait0();
        __syncthreads();
        if (it + 1 < NK) { load_stage((it + 1) & 1, (it + 1) * 32); cp_commit(); }

        const __nv_bfloat16* Ahb = Ah + (it & 1) * 5120;
        const __nv_bfloat16* Alb = Al + (it & 1) * 5120;
        const __nv_bfloat16* Bhb = Bh + (it & 1) * 5120;
        const __nv_bfloat16* Blb = Bl + (it & 1) * 5120;

        #pragma unroll
        for (int kk = 0; kk < 2; ++kk) {
            int k = kk * 16;
            unsigned ah[4][4], al[4][4];
            #pragma unroll
            for (int mt = 0; mt < 4; ++mt) {
                int off = (wm + mt * 16 + g) * STR + k + 2 * t;
                ah[mt][0] = *(const unsigned*)(Ahb + off);
                ah[mt][1] = *(const unsigned*)(Ahb + off + 8 * STR);
                ah[mt][2] = *(const unsigned*)(Ahb + off + 8);
                ah[mt][3] = *(const unsigned*)(Ahb + off + 8 * STR + 8);
                al[mt][0] = *(const unsigned*)(Alb + off);
                al[mt][1] = *(const unsigned*)(Alb + off + 8 * STR);
                al[mt][2] = *(const unsigned*)(Alb + off + 8);
                al[mt][3] = *(const unsigned*)(Alb + off + 8 * STR + 8);
            }
            #pragma unroll
            for (int nt = 0; nt < 4; ++nt) {
                int off = (wn + nt * 8 + g) * STR + k + 2 * t;
                unsigned bh0 = *(const unsigned*)(Bhb + off), bh1 = *(const unsigned*)(Bhb + off + 8);
                unsigned bl0 = *(const unsigned*)(Blb + off), bl1 = *(const unsigned*)(Blb + off + 8);
                #pragma unroll
                for (int mt = 0; mt < 4; ++mt)
                    mma3(acc[mt][nt], ah[mt], al[mt], bh0, bh1, bl0, bl1);
            }
        }
    }

    #pragma unroll
    for (int mt = 0; mt < 4; ++mt) {
        #pragma unroll
        for (int half = 0; half < 2; ++half) {
            int ml = wm + mt * 16 + g + half * 8;
            if (m0 + ml < cnt) {
                float w = swt[ml];
                float* op = out + (size_t)stok[ml] * HD + n0 + wn;
                #pragma unroll
                for (int nt = 0; nt < 4; ++nt) {
                    atomicAdd(op + nt * 8 + 2 * t,     w * acc[mt][nt][half * 2]);
                    atomicAdd(op + nt * 8 + 2 * t + 1, w * acc[mt][nt][half * 2 + 1]);
                }
            }
        }
    }
}

// ---------------- launch ----------------
extern "C" void kernel_launch(void* const* d_in, const int* in_sizes, int n_in,
                              void* d_out, int out_size) {
    const float* x  = (const float*)d_in[0];
    const float* gw = (const float*)d_in[1];
    const float* w1 = (const float*)d_in[2];
    const float* w3 = (const float*)d_in[3];
    const float* w2 = (const float*)d_in[4];
    float* out = (float*)d_out;

    cudaFuncSetAttribute(gemm1_kernel, cudaFuncAttributeMaxDynamicSharedMemorySize, 82432);
    cudaFuncSetAttribute(gemm2_kernel, cudaFuncAttributeMaxDynamicSharedMemorySize, 82944);

    __nv_bfloat16 *w1h, *w1l, *w3h, *w3l, *w2h, *w2l, *xh, *xl;
    cudaGetSymbolAddress((void**)&w1h, g_w1h);
    cudaGetSymbolAddress((void**)&w1l, g_w1l);
    cudaGetSymbolAddress((void**)&w3h, g_w3h);
    cudaGetSymbolAddress((void**)&w3l, g_w3l);
    cudaGetSymbolAddress((void**)&w2h, g_w2h);
    cudaGetSymbolAddress((void**)&w2l, g_w2l);
    cudaGetSymbolAddress((void**)&xh, g_xh);
    cudaGetSymbolAddress((void**)&xl, g_xl);

    zero_kernel<<<2048, 256>>>(out);
    router_kernel<<<TOKS, 256>>>(x, gw);
    offsets_kernel<<<1, 1>>>();
    split_kernel<<<4096, 256>>>(w1, w1h, w1l, SZW / 4);
    split_kernel<<<4096, 256>>>(w3, w3h, w3l, SZW / 4);
    split_kernel<<<4096, 256>>>(w2, w2h, w2l, SZW / 4);
    split_kernel<<<512,  256>>>(x,  xh,  xl,  SZX / 4);
    gemm1_kernel<<<dim3(TOKS / 128, ID / 64, NE), 256, 82432>>>();
    gemm2_kernel<<<dim3(TOKS / 128, HD / 128, NE), 256, 82944>>>(out);
}

// round 8
// speedup vs baseline: 5.9440x; 1.7906x over previous
#include <cuda_runtime.h>
#include <cuda_bf16.h>
#include <math.h>

#define TOKS 4096
#define HD   4096
#define ID   6400
#define NE   8
#define SZW  ((size_t)NE * ID * HD)
#define SZX  ((size_t)TOKS * HD)
#define HSLOT (2 * TOKS + 128)
#define SZH  ((size_t)HSLOT * ID)

// stage: Ah 16K, Al 16K, Bh 8K, Bl 8K = 48K; 2 stages + 1K tail
#define STG   49152
#define SMEMSZ (2 * STG + 1024)

// ---------------- device scratch ----------------
__device__ int   g_cnt[NE];
__device__ int   g_off[NE];
__device__ int   g_tok[NE][TOKS];
__device__ float g_wt [NE][TOKS];
__device__ __nv_bfloat16 g_w1h[SZW], g_w1l[SZW];
__device__ __nv_bfloat16 g_w3h[SZW], g_w3l[SZW];
__device__ __nv_bfloat16 g_w2h[SZW], g_w2l[SZW];
__device__ __nv_bfloat16 g_xh[SZX],  g_xl[SZX];
__device__ __nv_bfloat16 g_hh[SZH],  g_hl[SZH];

// ---------------- helpers ----------------
__device__ __forceinline__ unsigned su32(const void* p) {
    return (unsigned)__cvta_generic_to_shared(p);
}
__device__ __forceinline__ void cpasync16(unsigned dst, const void* src) {
    asm volatile("cp.async.cg.shared.global [%0], [%1], 16;\n" ::"r"(dst), "l"(src));
}
__device__ __forceinline__ void cp_commit() { asm volatile("cp.async.commit_group;\n"); }
__device__ __forceinline__ void cp_wait0()  { asm volatile("cp.async.wait_group 0;\n"); }
__device__ __forceinline__ void cp_wait1()  { asm volatile("cp.async.wait_group 1;\n"); }

__device__ __forceinline__ void ldsm4(unsigned* r, unsigned a) {
    asm volatile("ldmatrix.sync.aligned.m8n8.x4.shared.b16 {%0,%1,%2,%3}, [%4];"
                 : "=r"(r[0]), "=r"(r[1]), "=r"(r[2]), "=r"(r[3]) : "r"(a));
}
__device__ __forceinline__ void mmabf(float* c, const unsigned* a, unsigned b0, unsigned b1) {
    asm volatile(
        "mma.sync.aligned.m16n8k16.row.col.f32.bf16.bf16.f32 "
        "{%0,%1,%2,%3},{%4,%5,%6,%7},{%8,%9},{%0,%1,%2,%3};\n"
        : "+f"(c[0]), "+f"(c[1]), "+f"(c[2]), "+f"(c[3])
        : "r"(a[0]), "r"(a[1]), "r"(a[2]), "r"(a[3]), "r"(b0), "r"(b1));
}

__device__ __forceinline__ void split2(float a, float b, __nv_bfloat162& hi, __nv_bfloat162& lo) {
    __nv_bfloat16 ha = __float2bfloat16_rn(a);
    __nv_bfloat16 hb = __float2bfloat16_rn(b);
    hi = __halves2bfloat162(ha, hb);
    lo = __halves2bfloat162(__float2bfloat16_rn(a - __bfloat162float(ha)),
                            __float2bfloat16_rn(b - __bfloat162float(hb)));
}

// ---------------- operand split precompute ----------------
__global__ void split_kernel(const float* __restrict__ src, __nv_bfloat16* __restrict__ hi,
                             __nv_bfloat16* __restrict__ lo, size_t n4) {
    for (size_t i = (size_t)blockIdx.x * blockDim.x + threadIdx.x; i < n4;
         i += (size_t)gridDim.x * blockDim.x) {
        float4 v = ((const float4*)src)[i];
        __nv_bfloat162 h01, l01, h23, l23;
        split2(v.x, v.y, h01, l01);
        split2(v.z, v.w, h23, l23);
        ((__nv_bfloat162*)hi)[2 * i]     = h01;
        ((__nv_bfloat162*)hi)[2 * i + 1] = h23;
        ((__nv_bfloat162*)lo)[2 * i]     = l01;
        ((__nv_bfloat162*)lo)[2 * i + 1] = l23;
    }
}

// ---------------- zero output + counters ----------------
__global__ void zero_kernel(float* __restrict__ out) {
    size_t n4 = (size_t)TOKS * HD / 4;
    float4 z = make_float4(0.f, 0.f, 0.f, 0.f);
    for (size_t k = (size_t)blockIdx.x * blockDim.x + threadIdx.x; k < n4;
         k += (size_t)gridDim.x * blockDim.x)
        ((float4*)out)[k] = z;
    if (blockIdx.x == 0 && threadIdx.x < NE) g_cnt[threadIdx.x] = 0;
}

// ---------------- router ----------------
__global__ void router_kernel(const float* __restrict__ x, const float* __restrict__ gw) {
    __shared__ float sx[HD];
    __shared__ float slog[NE];
    int t = blockIdx.x;
    const float* xr = x + (size_t)t * HD;
    for (int k = threadIdx.x; k < HD / 4; k += blockDim.x)
        ((float4*)sx)[k] = ((const float4*)xr)[k];
    __syncthreads();
    int warp = threadIdx.x >> 5, lane = threadIdx.x & 31;
    float s = 0.f;
    const float* g = gw + (size_t)warp * HD;
    for (int k = lane; k < HD; k += 32) s += sx[k] * g[k];
    #pragma unroll
    for (int o = 16; o; o >>= 1) s += __shfl_xor_sync(0xffffffffu, s, o);
    if (lane == 0) slog[warp] = s;
    __syncthreads();
    if (threadIdx.x == 0) {
        int i1 = 0;
        #pragma unroll
        for (int e = 1; e < NE; ++e) if (slog[e] > slog[i1]) i1 = e;
        int i2 = (i1 == 0) ? 1 : 0;
        #pragma unroll
        for (int e = 0; e < NE; ++e) if (e != i1 && slog[e] > slog[i2]) i2 = e;
        float p1 = 1.f / (1.f + expf(slog[i2] - slog[i1]));
        float p2 = 1.f - p1;
        int s1 = atomicAdd(&g_cnt[i1], 1);
        g_tok[i1][s1] = t; g_wt[i1][s1] = p1;
        int s2 = atomicAdd(&g_cnt[i2], 1);
        g_tok[i2][s2] = t; g_wt[i2][s2] = p2;
    }
}

__global__ void offsets_kernel() {
    int o = 0;
    for (int e = 0; e < NE; ++e) { g_off[e] = o; o += g_cnt[e]; }
}

// =================================================================
// GEMM1: per CTA 128 toks x 32 i-cols, B = [w1(32) | w3(32)] rows
// 8 warps: 4 m-tiles x 2 n-tiles(gate/up). 3-term bf16, ldmatrix.
// =================================================================
__global__ void __launch_bounds__(256, 2) gemm1_kernel() {
    int e = blockIdx.z;
    int cnt = g_cnt[e];
    int m0 = blockIdx.x * 128;
    if (m0 >= cnt) return;
    int n0 = blockIdx.y * 32;

    extern __shared__ char dynsm[];
    unsigned sb = su32(dynsm);
    int* stok = (int*)(dynsm + 2 * STG);

    int tid = threadIdx.x;
    if (tid < 128) {
        int s = m0 + tid;
        stok[tid] = (s < cnt) ? g_tok[e][s] : 0;
    }
    __syncthreads();

    const __nv_bfloat16* w1h = g_w1h + (size_t)e * ID * HD;
    const __nv_bfloat16* w3h = g_w3h + (size_t)e * ID * HD;
    long long dXL = (char*)g_xl - (char*)g_xh;
    long long dW1 = (char*)g_w1l - (char*)g_w1h;
    long long dW3 = (char*)g_w3l - (char*)g_w3h;

    // ---- per-thread cp.async plan: 4 A-chunks + 2 B-chunks (hi), lo via delta
    const __nv_bfloat16* srcA[4];
    unsigned dstA[4];
    #pragma unroll
    for (int p = 0; p < 4; ++p) {
        int cid = tid + p * 256;
        int r = cid >> 3, c = cid & 7;
        dstA[p] = r * 128 + ((c ^ (r & 7)) << 4);
        srcA[p] = g_xh + (size_t)stok[r] * HD + c * 8;
    }
    const __nv_bfloat16* srcB[2];
    unsigned dstB[2];
    long long dBL[2];
    #pragma unroll
    for (int p = 0; p < 2; ++p) {
        int cid = tid + p * 256;
        int r = cid >> 3, c = cid & 7;                  // r in 0..63
        dstB[p] = 32768 + r * 128 + ((c ^ (r & 7)) << 4);
        srcB[p] = (r < 32) ? w1h + (size_t)(n0 + r) * HD + c * 8
                           : w3h + (size_t)(n0 + r - 32) * HD + c * 8;
        dBL[p] = (r < 32) ? dW1 : dW3;
    }

    auto load_stage = [&](int buf) {
        unsigned base = sb + (unsigned)buf * STG;
        #pragma unroll
        for (int p = 0; p < 4; ++p) {
            cpasync16(base + dstA[p], srcA[p]);
            cpasync16(base + 16384 + dstA[p], (const char*)srcA[p] + dXL);
            srcA[p] += 64;
        }
        #pragma unroll
        for (int p = 0; p < 2; ++p) {
            cpasync16(base + dstB[p], srcB[p]);
            cpasync16(base + 8192 + dstB[p], (const char*)srcB[p] + dBL[p]);
            srcB[p] += 64;
        }
    };

    int warp = tid >> 5, lane = tid & 31;
    int wm = (warp & 3) * 32, wn = warp >> 2;           // wn: 0=gate, 1=up
    int sub = lane >> 3;
    int arow_off = (lane & 7) + ((sub & 1) << 3), asel = sub >> 1;
    int brow_off = (lane & 7) + ((sub >> 1) << 3), bsel = sub & 1;

    // ldmatrix row bases (per thread)
    int rA0 = wm + arow_off,      rA1 = wm + 16 + arow_off;
    int rB0 = wn * 32 + brow_off, rB1 = wn * 32 + 16 + brow_off;
    unsigned aB0 = rA0 * 128, aX0 = (unsigned)(rA0 & 7);
    unsigned aB1 = rA1 * 128, aX1 = (unsigned)(rA1 & 7);
    unsigned bB0 = rB0 * 128, bX0 = (unsigned)(rB0 & 7);
    unsigned bB1 = rB1 * 128, bX1 = (unsigned)(rB1 & 7);

    float acc[2][4][4];
    #pragma unroll
    for (int i = 0; i < 2; ++i)
        #pragma unroll
        for (int j = 0; j < 4; ++j)
            #pragma unroll
            for (int k = 0; k < 4; ++k) acc[i][j][k] = 0.f;

    const int NS = HD / 64;  // 64
    load_stage(0); cp_commit();

    for (int it = 0; it < NS; ++it) {
        if (it + 1 < NS) { load_stage((it + 1) & 1); cp_commit(); cp_wait1(); }
        else cp_wait0();
        __syncthreads();
        unsigned base = sb + (unsigned)(it & 1) * STG;

        #pragma unroll
        for (int kk = 0; kk < 4; ++kk) {
            unsigned ca = (unsigned)(2 * kk + asel);
            unsigned cb = (unsigned)(2 * kk + bsel);
            unsigned ah[2][4], al[2][4], bh[2][4], bl[2][4];
            ldsm4(ah[0], base + aB0 + ((ca ^ aX0) << 4));
            ldsm4(ah[1], base + aB1 + ((ca ^ aX1) << 4));
            ldsm4(al[0], base + 16384 + aB0 + ((ca ^ aX0) << 4));
            ldsm4(al[1], base + 16384 + aB1 + ((ca ^ aX1) << 4));
            ldsm4(bh[0], base + 32768 + bB0 + ((cb ^ bX0) << 4));
            ldsm4(bh[1], base + 32768 + bB1 + ((cb ^ bX1) << 4));
            ldsm4(bl[0], base + 40960 + bB0 + ((cb ^ bX0) << 4));
            ldsm4(bl[1], base + 40960 + bB1 + ((cb ^ bX1) << 4));
            #pragma unroll
            for (int nt = 0; nt < 4; ++nt) {
                int gsel = nt >> 1, psel = (nt & 1) * 2;
                unsigned b0h = bh[gsel][psel], b1h = bh[gsel][psel + 1];
                unsigned b0l = bl[gsel][psel], b1l = bl[gsel][psel + 1];
                #pragma unroll
                for (int mt = 0; mt < 2; ++mt) {
                    mmabf(acc[mt][nt], al[mt], b0h, b1h);
                    mmabf(acc[mt][nt], ah[mt], b0l, b1l);
                    mmabf(acc[mt][nt], ah[mt], b0h, b1h);
                }
            }
        }
        __syncthreads();
    }

    // ---- epilogue: exchange gate/up via smem, silu*up, split, store
    float* sg = (float*)dynsm;                 // [128][33]
    float* sup = sg + 128 * 33;
    int g = lane >> 2, t4 = lane & 3;
    float* darr = (wn == 0) ? sg : sup;
    #pragma unroll
    for (int mt = 0; mt < 2; ++mt)
        #pragma unroll
        for (int nt = 0; nt < 4; ++nt)
            #pragma unroll
            for (int half = 0; half < 2; ++half) {
                int row = wm + mt * 16 + g + half * 8;
                int col = nt * 8 + 2 * t4;
                darr[row * 33 + col]     = acc[mt][nt][half * 2];
                darr[row * 33 + col + 1] = acc[mt][nt][half * 2 + 1];
            }
    __syncthreads();

    {
        int row = tid >> 1, cb = (tid & 1) * 16;
        bool live = (m0 + row < cnt);
        if (live) {
            size_t ro = (size_t)(g_off[e] + m0 + row) * ID + n0 + cb;
            #pragma unroll
            for (int j = 0; j < 16; j += 2) {
                float g0 = sg[row * 33 + cb + j],     u0 = sup[row * 33 + cb + j];
                float g1 = sg[row * 33 + cb + j + 1], u1 = sup[row * 33 + cb + j + 1];
                float h0 = g0 / (1.f + __expf(-g0)) * u0;
                float h1 = g1 / (1.f + __expf(-g1)) * u1;
                __nv_bfloat162 hi, lo;
                split2(h0, h1, hi, lo);
                *(__nv_bfloat162*)(g_hh + ro + j) = hi;
                *(__nv_bfloat162*)(g_hl + ro + j) = lo;
            }
        }
    }
}

// =================================================================
// GEMM2: per CTA 128 toks x 64 out-cols. 8 warps 4m x 2n.
// =================================================================
__global__ void __launch_bounds__(256, 2) gemm2_kernel(float* __restrict__ out) {
    int e = blockIdx.z;
    int cnt = g_cnt[e];
    int m0 = blockIdx.x * 128;
    if (m0 >= cnt) return;
    int n0 = blockIdx.y * 64;

    extern __shared__ char dynsm[];
    unsigned sb = su32(dynsm);
    int*   stok = (int*)(dynsm + 2 * STG);
    float* swt  = (float*)(stok + 128);

    int tid = threadIdx.x;
    if (tid < 128) {
        int s = m0 + tid;
        stok[tid] = (s < cnt) ? g_tok[e][s] : 0;
        swt[tid]  = (s < cnt) ? g_wt[e][s] : 0.f;
    }
    __syncthreads();

    size_t hbase = (size_t)(g_off[e] + m0) * ID;
    const __nv_bfloat16* w2h = g_w2h + (size_t)e * HD * ID;
    long long dHL = (char*)g_hl - (char*)g_hh;
    long long dW2 = (char*)g_w2l - (char*)g_w2h;

    const __nv_bfloat16* srcA[4];
    unsigned dstA[4];
    #pragma unroll
    for (int p = 0; p < 4; ++p) {
        int cid = tid + p * 256;
        int r = cid >> 3, c = cid & 7;
        dstA[p] = r * 128 + ((c ^ (r & 7)) << 4);
        srcA[p] = g_hh + hbase + (size_t)r * ID + c * 8;
    }
    const __nv_bfloat16* srcB[2];
    unsigned dstB[2];
    #pragma unroll
    for (int p = 0; p < 2; ++p) {
        int cid = tid + p * 256;
        int r = cid >> 3, c = cid & 7;
        dstB[p] = 32768 + r * 128 + ((c ^ (r & 7)) << 4);
        srcB[p] = w2h + (size_t)(n0 + r) * ID + c * 8;
    }

    auto load_stage = [&](int buf) {
        unsigned base = sb + (unsigned)buf * STG;
        #pragma unroll
        for (int p = 0; p < 4; ++p) {
            cpasync16(base + dstA[p], srcA[p]);
            cpasync16(base + 16384 + dstA[p], (const char*)srcA[p] + dHL);
            srcA[p] += 64;
        }
        #pragma unroll
        for (int p = 0; p < 2; ++p) {
            cpasync16(base + dstB[p], srcB[p]);
            cpasync16(base + 8192 + dstB[p], (const char*)srcB[p] + dW2);
            srcB[p] += 64;
        }
    };

    int warp = tid >> 5, lane = tid & 31;
    int wm = (warp & 3) * 32, wn = warp >> 2;
    int sub = lane >> 3;
    int arow_off = (lane & 7) + ((sub & 1) << 3), asel = sub >> 1;
    int brow_off = (lane & 7) + ((sub >> 1) << 3), bsel = sub & 1;

    int rA0 = wm + arow_off,      rA1 = wm + 16 + arow_off;
    int rB0 = wn * 32 + brow_off, rB1 = wn * 32 + 16 + brow_off;
    unsigned aB0 = rA0 * 128, aX0 = (unsigned)(rA0 & 7);
    unsigned aB1 = rA1 * 128, aX1 = (unsigned)(rA1 & 7);
    unsigned bB0 = rB0 * 128, bX0 = (unsigned)(rB0 & 7);
    unsigned bB1 = rB1 * 128, bX1 = (unsigned)(rB1 & 7);

    float acc[2][4][4];
    #pragma unroll
    for (int i = 0; i < 2; ++i)
        #pragma unroll
        for (int j = 0; j < 4; ++j)
            #pragma unroll
            for (int k = 0; k < 4; ++k) acc[i][j][k] = 0.f;

    const int NS = ID / 64;  // 100
    load_stage(0); cp_commit();

    for (int it = 0; it < NS; ++it) {
        if (it + 1 < NS) { load_stage((it + 1) & 1); cp_commit(); cp_wait1(); }
        else cp_wait0();
        __syncthreads();
        unsigned base = sb + (unsigned)(it & 1) * STG;

        #pragma unroll
        for (int kk = 0; kk < 4; ++kk) {
            unsigned ca = (unsigned)(2 * kk + asel);
            unsigned cb = (unsigned)(2 * kk + bsel);
            unsigned ah[2][4], al[2][4], bh[2][4], bl[2][4];
            ldsm4(ah[0], base + aB0 + ((ca ^ aX0) << 4));
            ldsm4(ah[1], base + aB1 + ((ca ^ aX1) << 4));
            ldsm4(al[0], base + 16384 + aB0 + ((ca ^ aX0) << 4));
            ldsm4(al[1], base + 16384 + aB1 + ((ca ^ aX1) << 4));
            ldsm4(bh[0], base + 32768 + bB0 + ((cb ^ bX0) << 4));
            ldsm4(bh[1], base + 32768 + bB1 + ((cb ^ bX1) << 4));
            ldsm4(bl[0], base + 40960 + bB0 + ((cb ^ bX0) << 4));
            ldsm4(bl[1], base + 40960 + bB1 + ((cb ^ bX1) << 4));
            #pragma unroll
            for (int nt = 0; nt < 4; ++nt) {
                int gsel = nt >> 1, psel = (nt & 1) * 2;
                unsigned b0h = bh[gsel][psel], b1h = bh[gsel][psel + 1];
                unsigned b0l = bl[gsel][psel], b1l = bl[gsel][psel + 1];
                #pragma unroll
                for (int mt = 0; mt < 2; ++mt) {
                    mmabf(acc[mt][nt], al[mt], b0h, b1h);
                    mmabf(acc[mt][nt], ah[mt], b0l, b1l);
                    mmabf(acc[mt][nt], ah[mt], b0h, b1h);
                }
            }
        }
        __syncthreads();
    }

    int g = lane >> 2, t4 = lane & 3;
    #pragma unroll
    for (int mt = 0; mt < 2; ++mt)
        #pragma unroll
        for (int half = 0; half < 2; ++half) {
            int ml = wm + mt * 16 + g + half * 8;
            if (m0 + ml < cnt) {
                float w = swt[ml];
                float* op = out + (size_t)stok[ml] * HD + n0 + wn * 32;
                #pragma unroll
                for (int nt = 0; nt < 4; ++nt) {
                    atomicAdd(op + nt * 8 + 2 * t4,     w * acc[mt][nt][half * 2]);
                    atomicAdd(op + nt * 8 + 2 * t4 + 1, w * acc[mt][nt][half * 2 + 1]);
                }
            }
        }
}

// ---------------- launch ----------------
extern "C" void kernel_launch(void* const* d_in, const int* in_sizes, int n_in,
                              void* d_out, int out_size) {
    const float* x  = (const float*)d_in[0];
    const float* gw = (const float*)d_in[1];
    const float* w1 = (const float*)d_in[2];
    const float* w3 = (const float*)d_in[3];
    const float* w2 = (const float*)d_in[4];
    float* out = (float*)d_out;

    cudaFuncSetAttribute(gemm1_kernel, cudaFuncAttributeMaxDynamicSharedMemorySize, SMEMSZ);
    cudaFuncSetAttribute(gemm2_kernel, cudaFuncAttributeMaxDynamicSharedMemorySize, SMEMSZ);

    __nv_bfloat16 *w1h, *w1l, *w3h, *w3l, *w2h, *w2l, *xh, *xl;
    cudaGetSymbolAddress((void**)&w1h, g_w1h);
    cudaGetSymbolAddress((void**)&w1l, g_w1l);
    cudaGetSymbolAddress((void**)&w3h, g_w3h);
    cudaGetSymbolAddress((void**)&w3l, g_w3l);
    cudaGetSymbolAddress((void**)&w2h, g_w2h);
    cudaGetSymbolAddress((void**)&w2l, g_w2l);
    cudaGetSymbolAddress((void**)&xh, g_xh);
    cudaGetSymbolAddress((void**)&xl, g_xl);

    zero_kernel<<<2048, 256>>>(out);
    router_kernel<<<TOKS, 256>>>(x, gw);
    offsets_kernel<<<1, 1>>>();
    split_kernel<<<4096, 256>>>(w1, w1h, w1l, SZW / 4);
    split_kernel<<<4096, 256>>>(w3, w3h, w3l, SZW / 4);
    split_kernel<<<4096, 256>>>(w2, w2h, w2l, SZW / 4);
    split_kernel<<<512,  256>>>(x,  xh,  xl,  SZX / 4);
    gemm1_kernel<<<dim3(TOKS / 128, ID / 32, NE), 256, SMEMSZ>>>();
    gemm2_kernel<<<dim3(TOKS / 128, HD / 64, NE), 256, SMEMSZ>>>(out);
}

// round 10
// speedup vs baseline: 5.9588x; 1.0025x over previous
#include <cuda_runtime.h>
#include <cuda_bf16.h>
#include <math.h>

#define TOKS 4096
#define HD   4096
#define ID   6400
#define NE   8
#define SZW  ((size_t)NE * ID * HD)
#define SZX  ((size_t)TOKS * HD)
#define HSLOT (2 * TOKS + 256)
#define SZH  ((size_t)HSLOT * ID)

// stage: Ah 32K | Al 32K | Bh 16K | Bl 16K = 96K; 2 stages + 2K tail
#define STG    98304
#define SMEMSZ (2 * STG + 2048)

// ---------------- device scratch (hi/lo planes at fixed delta) ----------------
__device__ int   g_cnt[NE];
__device__ int   g_off[NE];
__device__ int   g_tok[NE][TOKS];
__device__ float g_wt [NE][TOKS];
__device__ __nv_bfloat16 g_w1[2][SZW];
__device__ __nv_bfloat16 g_w3[2][SZW];
__device__ __nv_bfloat16 g_w2[2][SZW];
__device__ __nv_bfloat16 g_x [2][SZX];
__device__ __nv_bfloat16 g_h [2][SZH];

// ---------------- helpers ----------------
__device__ __forceinline__ unsigned su32(const void* p) {
    return (unsigned)__cvta_generic_to_shared(p);
}
__device__ __forceinline__ void cpasync16(unsigned dst, const void* src) {
    asm volatile("cp.async.cg.shared.global [%0], [%1], 16;\n" ::"r"(dst), "l"(src));
}
__device__ __forceinline__ void cp_commit() { asm volatile("cp.async.commit_group;\n"); }
__device__ __forceinline__ void cp_wait0()  { asm volatile("cp.async.wait_group 0;\n"); }
__device__ __forceinline__ void cp_wait1()  { asm volatile("cp.async.wait_group 1;\n"); }

__device__ __forceinline__ void ldsm4(unsigned* r, unsigned a) {
    asm volatile("ldmatrix.sync.aligned.m8n8.x4.shared.b16 {%0,%1,%2,%3}, [%4];"
                 : "=r"(r[0]), "=r"(r[1]), "=r"(r[2]), "=r"(r[3]) : "r"(a));
}
__device__ __forceinline__ void mmabf(float* c, const unsigned* a, unsigned b0, unsigned b1) {
    asm volatile(
        "mma.sync.aligned.m16n8k16.row.col.f32.bf16.bf16.f32 "
        "{%0,%1,%2,%3},{%4,%5,%6,%7},{%8,%9},{%0,%1,%2,%3};\n"
        : "+f"(c[0]), "+f"(c[1]), "+f"(c[2]), "+f"(c[3])
        : "r"(a[0]), "r"(a[1]), "r"(a[2]), "r"(a[3]), "r"(b0), "r"(b1));
}

__device__ __forceinline__ void split2(float a, float b, __nv_bfloat162& hi, __nv_bfloat162& lo) {
    __nv_bfloat16 ha = __float2bfloat16_rn(a);
    __nv_bfloat16 hb = __float2bfloat16_rn(b);
    hi = __halves2bfloat162(ha, hb);
    lo = __halves2bfloat162(__float2bfloat16_rn(a - __bfloat162float(ha)),
                            __float2bfloat16_rn(b - __bfloat162float(hb)));
}

// ---------------- operand split precompute ----------------
__global__ void split_kernel(const float* __restrict__ src, __nv_bfloat16* __restrict__ hi,
                             __nv_bfloat16* __restrict__ lo, size_t n4) {
    for (size_t i = (size_t)blockIdx.x * blockDim.x + threadIdx.x; i < n4;
         i += (size_t)gridDim.x * blockDim.x) {
        float4 v = ((const float4*)src)[i];
        __nv_bfloat162 h01, l01, h23, l23;
        split2(v.x, v.y, h01, l01);
        split2(v.z, v.w, h23, l23);
        ((__nv_bfloat162*)hi)[2 * i]     = h01;
        ((__nv_bfloat162*)hi)[2 * i + 1] = h23;
        ((__nv_bfloat162*)lo)[2 * i]     = l01;
        ((__nv_bfloat162*)lo)[2 * i + 1] = l23;
    }
}

// ---------------- zero output + counters ----------------
__global__ void zero_kernel(float* __restrict__ out) {
    size_t n4 = (size_t)TOKS * HD / 4;
    float4 z = make_float4(0.f, 0.f, 0.f, 0.f);
    for (size_t k = (size_t)blockIdx.x * blockDim.x + threadIdx.x; k < n4;
         k += (size_t)gridDim.x * blockDim.x)
        ((float4*)out)[k] = z;
    if (blockIdx.x == 0 && threadIdx.x < NE) g_cnt[threadIdx.x] = 0;
}

// ---------------- router ----------------
__global__ void router_kernel(const float* __restrict__ x, const float* __restrict__ gw) {
    __shared__ float sx[HD];
    __shared__ float slog[NE];
    int t = blockIdx.x;
    const float* xr = x + (size_t)t * HD;
    for (int k = threadIdx.x; k < HD / 4; k += blockDim.x)
        ((float4*)sx)[k] = ((const float4*)xr)[k];
    __syncthreads();
    int warp = threadIdx.x >> 5, lane = threadIdx.x & 31;
    float s = 0.f;
    const float* g = gw + (size_t)warp * HD;
    for (int k = lane; k < HD; k += 32) s += sx[k] * g[k];
    #pragma unroll
    for (int o = 16; o; o >>= 1) s += __shfl_xor_sync(0xffffffffu, s, o);
    if (lane == 0) slog[warp] = s;
    __syncthreads();
    if (threadIdx.x == 0) {
        int i1 = 0;
        #pragma unroll
        for (int e = 1; e < NE; ++e) if (slog[e] > slog[i1]) i1 = e;
        int i2 = (i1 == 0) ? 1 : 0;
        #pragma unroll
        for (int e = 0; e < NE; ++e) if (e != i1 && slog[e] > slog[i2]) i2 = e;
        float p1 = 1.f / (1.f + expf(slog[i2] - slog[i1]));
        float p2 = 1.f - p1;
        int s1 = atomicAdd(&g_cnt[i1], 1);
        g_tok[i1][s1] = t; g_wt[i1][s1] = p1;
        int s2 = atomicAdd(&g_cnt[i2], 1);
        g_tok[i2][s2] = t; g_wt[i2][s2] = p2;
    }
}

__global__ void offsets_kernel() {
    int o = 0;
    for (int e = 0; e < NE; ++e) { g_off[e] = o; o += g_cnt[e]; }
}

// =================================================================
// GEMM1: tile 256 toks x (64 gate | 64 up), K=HD, 512 thr, warp 32x64
// =================================================================
__global__ void __launch_bounds__(512, 1) gemm1_kernel() {
    int e = blockIdx.z;
    int cnt = g_cnt[e];
    int m0 = blockIdx.x * 256;
    if (m0 >= cnt) return;
    int n0 = blockIdx.y * 64;

    extern __shared__ char dynsm[];
    unsigned sb = su32(dynsm);
    int* stok = (int*)(dynsm + 2 * STG);

    int tid = threadIdx.x;
    if (tid < 256) {
        int s = m0 + tid;
        stok[tid] = (s < cnt) ? g_tok[e][s] : 0;
    }
    __syncthreads();

    // per-thread cp.async plan
    const __nv_bfloat16* pA[4];
    unsigned dA[4];
    #pragma unroll
    for (int p = 0; p < 4; ++p) {
        int cid = tid + p * 512;               // [0,2048): r in [0,256)
        int r = cid >> 3, c = cid & 7;
        dA[p] = r * 128 + ((c ^ (r & 7)) << 4);
        pA[p] = g_x[0] + (size_t)stok[r] * HD + c * 8;
    }
    const __nv_bfloat16* pB[2];
    unsigned dB[2];
    #pragma unroll
    for (int p = 0; p < 2; ++p) {
        int cid = tid + p * 512;               // [0,1024): r in [0,128)
        int r = cid >> 3, c = cid & 7;
        dB[p] = 65536 + r * 128 + ((c ^ (r & 7)) << 4);
        pB[p] = (r < 64) ? g_w1[0] + ((size_t)e * ID + n0 + r) * HD + c * 8
                         : g_w3[0] + ((size_t)e * ID + n0 + r - 64) * HD + c * 8;
    }

    auto load_stage = [&](int buf) {
        unsigned base = sb + (unsigned)buf * STG;
        #pragma unroll
        for (int p = 0; p < 4; ++p) {
            cpasync16(base + dA[p], pA[p]);
            cpasync16(base + 32768 + dA[p], pA[p] + SZX);
            pA[p] += 64;
        }
        #pragma unroll
        for (int p = 0; p < 2; ++p) {
            cpasync16(base + dB[p], pB[p]);
            cpasync16(base + 16384 + dB[p], pB[p] + SZW);
            pB[p] += 64;
        }
    };

    int warp = tid >> 5, lane = tid & 31;
    int wm = (warp & 7) * 32, wn = (warp >> 3) * 64;
    int sub = lane >> 3;
    int arow_off = (lane & 7) + ((sub & 1) << 3), asel = sub >> 1;
    int brow_off = (lane & 7) + ((sub >> 1) << 3), bsel = sub & 1;

    unsigned aB[2], aX[2], bBs[4], bXs[4];
    #pragma unroll
    for (int i = 0; i < 2; ++i) {
        int r = wm + i * 16 + arow_off;
        aB[i] = r * 128; aX[i] = (unsigned)(r & 7);
    }
    #pragma unroll
    for (int j = 0; j < 4; ++j) {
        int r = wn + j * 16 + brow_off;
        bBs[j] = 65536 + r * 128; bXs[j] = (unsigned)(r & 7);
    }

    float acc[2][8][4];
    #pragma unroll
    for (int i = 0; i < 2; ++i)
        #pragma unroll
        for (int j = 0; j < 8; ++j)
            #pragma unroll
            for (int k = 0; k < 4; ++k) acc[i][j][k] = 0.f;

    const int NS = HD / 64;  // 64
    load_stage(0); cp_commit();

    for (int it = 0; it < NS; ++it) {
        if (it + 1 < NS) { load_stage((it + 1) & 1); cp_commit(); cp_wait1(); }
        else cp_wait0();
        __syncthreads();
        unsigned base = sb + (unsigned)(it & 1) * STG;

        #pragma unroll
        for (int kk = 0; kk < 4; ++kk) {
            unsigned ca = (unsigned)(2 * kk + asel);
            unsigned cb = (unsigned)(2 * kk + bsel);
            unsigned ah[2][4], al[2][4];
            #pragma unroll
            for (int i = 0; i < 2; ++i) {
                ldsm4(ah[i], base + aB[i] + ((ca ^ aX[i]) << 4));
                ldsm4(al[i], base + 32768 + aB[i] + ((ca ^ aX[i]) << 4));
            }
            #pragma unroll
            for (int j = 0; j < 4; ++j) {
                unsigned bh[4], bl[4];
                ldsm4(bh, base + bBs[j] + ((cb ^ bXs[j]) << 4));
                ldsm4(bl, base + 16384 + bBs[j] + ((cb ^ bXs[j]) << 4));
                #pragma unroll
                for (int ntl = 0; ntl < 2; ++ntl) {
                    int nt = j * 2 + ntl;
                    unsigned b0h = bh[ntl * 2], b1h = bh[ntl * 2 + 1];
                    unsigned b0l = bl[ntl * 2], b1l = bl[ntl * 2 + 1];
                    #pragma unroll
                    for (int mt = 0; mt < 2; ++mt) {
                        mmabf(acc[mt][nt], al[mt], b0h, b1h);
                        mmabf(acc[mt][nt], ah[mt], b0l, b1l);
                        mmabf(acc[mt][nt], ah[mt], b0h, b1h);
                    }
                }
            }
        }
        __syncthreads();
    }

    // ---- epilogue: dump accs to smem, pair gate/up, silu, split, store
    float* sacc = (float*)dynsm;               // [256][132]
    int g = lane >> 2, t4 = lane & 3;
    #pragma unroll
    for (int mt = 0; mt < 2; ++mt)
        #pragma unroll
        for (int nt = 0; nt < 8; ++nt)
            #pragma unroll
            for (int half = 0; half < 2; ++half) {
                int row = wm + mt * 16 + g + half * 8;
                int col = wn + nt * 8 + 2 * t4;
                sacc[row * 132 + col]     = acc[mt][nt][half * 2];
                sacc[row * 132 + col + 1] = acc[mt][nt][half * 2 + 1];
            }
    __syncthreads();

    {
        int row = tid >> 1, cb0 = (tid & 1) * 32;
        if (m0 + row < cnt) {
            size_t ro = (size_t)(g_off[e] + m0 + row) * ID + n0 + cb0;
            const float* sr = sacc + row * 132 + cb0;
            #pragma unroll
            for (int j = 0; j < 32; j += 2) {
                float g0 = sr[j],     u0 = sr[64 + j];
                float g1 = sr[j + 1], u1 = sr[64 + j + 1];
                float h0 = g0 / (1.f + __expf(-g0)) * u0;
                float h1 = g1 / (1.f + __expf(-g1)) * u1;
                __nv_bfloat162 hi, lo;
                split2(h0, h1, hi, lo);
                *(__nv_bfloat162*)(g_h[0] + ro + j) = hi;
                *(__nv_bfloat162*)(g_h[1] + ro + j) = lo;
            }
        }
    }
}

// =================================================================
// GEMM2: tile 256 toks x 128 out-cols, K=ID, 512 thr, warp 32x64
// =================================================================
__global__ void __launch_bounds__(512, 1) gemm2_kernel(float* __restrict__ out) {
    int e = blockIdx.z;
    int cnt = g_cnt[e];
    int m0 = blockIdx.x * 256;
    if (m0 >= cnt) return;
    int n0 = blockIdx.y * 128;

    extern __shared__ char dynsm[];
    unsigned sb = su32(dynsm);
    int*   stok = (int*)(dynsm + 2 * STG);
    float* swt  = (float*)(stok + 256);

    int tid = threadIdx.x;
    if (tid < 256) {
        int s = m0 + tid;
        stok[tid] = (s < cnt) ? g_tok[e][s] : 0;
        swt[tid]  = (s < cnt) ? g_wt[e][s] : 0.f;
    }
    __syncthreads();

    size_t hbase = (size_t)(g_off[e] + m0) * ID;

    const __nv_bfloat16* pA[4];
    unsigned dA[4];
    #pragma unroll
    for (int p = 0; p < 4; ++p) {
        int cid = tid + p * 512;
        int r = cid >> 3, c = cid & 7;
        dA[p] = r * 128 + ((c ^ (r & 7)) << 4);
        pA[p] = g_h[0] + hbase + (size_t)r * ID + c * 8;
    }
    const __nv_bfloat16* pB[2];
    unsigned dB[2];
    #pragma unroll
    for (int p = 0; p < 2; ++p) {
        int cid = tid + p * 512;
        int r = cid >> 3, c = cid & 7;
        dB[p] = 65536 + r * 128 + ((c ^ (r & 7)) << 4);
        pB[p] = g_w2[0] + ((size_t)e * HD + n0 + r) * ID + c * 8;
    }

    auto load_stage = [&](int buf) {
        unsigned base = sb + (unsigned)buf * STG;
        #pragma unroll
        for (int p = 0; p < 4; ++p) {
            cpasync16(base + dA[p], pA[p]);
            cpasync16(base + 32768 + dA[p], pA[p] + SZH);
            pA[p] += 64;
        }
        #pragma unroll
        for (int p = 0; p < 2; ++p) {
            cpasync16(base + dB[p], pB[p]);
            cpasync16(base + 16384 + dB[p], pB[p] + SZW);
            pB[p] += 64;
        }
    };

    int warp = tid >> 5, lane = tid & 31;
    int wm = (warp & 7) * 32, wn = (warp >> 3) * 64;
    int sub = lane >> 3;
    int arow_off = (lane & 7) + ((sub & 1) << 3), asel = sub >> 1;
    int brow_off = (lane & 7) + ((sub >> 1) << 3), bsel = sub & 1;

    unsigned aB[2], aX[2], bBs[4], bXs[4];
    #pragma unroll
    for (int i = 0; i < 2; ++i) {
        int r = wm + i * 16 + arow_off;
        aB[i] = r * 128; aX[i] = (unsigned)(r & 7);
    }
    #pragma unroll
    for (int j = 0; j < 4; ++j) {
        int r = wn + j * 16 + brow_off;
        bBs[j] = 65536 + r * 128; bXs[j] = (unsigned)(r & 7);
    }

    float acc[2][8][4];
    #pragma unroll
    for (int i = 0; i < 2; ++i)
        #pragma unroll
        for (int j = 0; j < 8; ++j)
            #pragma unroll
            for (int k = 0; k < 4; ++k) acc[i][j][k] = 0.f;

    const int NS = ID / 64;  // 100
    load_stage(0); cp_commit();

    for (int it = 0; it < NS; ++it) {
        if (it + 1 < NS) { load_stage((it + 1) & 1); cp_commit(); cp_wait1(); }
        else cp_wait0();
        __syncthreads();
        unsigned base = sb + (unsigned)(it & 1) * STG;

        #pragma unroll
        for (int kk = 0; kk < 4; ++kk) {
            unsigned ca = (unsigned)(2 * kk + asel);
            unsigned cb = (unsigned)(2 * kk + bsel);
            unsigned ah[2][4], al[2][4];
            #pragma unroll
            for (int i = 0; i < 2; ++i) {
                ldsm4(ah[i], base + aB[i] + ((ca ^ aX[i]) << 4));
                ldsm4(al[i], base + 32768 + aB[i] + ((ca ^ aX[i]) << 4));
            }
            #pragma unroll
            for (int j = 0; j < 4; ++j) {
                unsigned bh[4], bl[4];
                ldsm4(bh, base + bBs[j] + ((cb ^ bXs[j]) << 4));
                ldsm4(bl, base + 16384 + bBs[j] + ((cb ^ bXs[j]) << 4));
                #pragma unroll
                for (int ntl = 0; ntl < 2; ++ntl) {
                    int nt = j * 2 + ntl;
                    unsigned b0h = bh[ntl * 2], b1h = bh[ntl * 2 + 1];
                    unsigned b0l = bl[ntl * 2], b1l = bl[ntl * 2 + 1];
                    #pragma unroll
                    for (int mt = 0; mt < 2; ++mt) {
                        mmabf(acc[mt][nt], al[mt], b0h, b1h);
                        mmabf(acc[mt][nt], ah[mt], b0l, b1l);
                        mmabf(acc[mt][nt], ah[mt], b0h, b1h);
                    }
                }
            }
        }
        __syncthreads();
    }

    int g = lane >> 2, t4 = lane & 3;
    #pragma unroll
    for (int mt = 0; mt < 2; ++mt)
        #pragma unroll
        for (int half = 0; half < 2; ++half) {
            int ml = wm + mt * 16 + g + half * 8;
            if (m0 + ml < cnt) {
                float w = swt[ml];
                float* op = out + (size_t)stok[ml] * HD + n0 + wn;
                #pragma unroll
                for (int nt = 0; nt < 8; ++nt) {
                    atomicAdd(op + nt * 8 + 2 * t4,     w * acc[mt][nt][half * 2]);
                    atomicAdd(op + nt * 8 + 2 * t4 + 1, w * acc[mt][nt][half * 2 + 1]);
                }
            }
        }
}

// ---------------- launch ----------------
extern "C" void kernel_launch(void* const* d_in, const int* in_sizes, int n_in,
                              void* d_out, int out_size) {
    const float* x  = (const float*)d_in[0];
    const float* gw = (const float*)d_in[1];
    const float* w1 = (const float*)d_in[2];
    const float* w3 = (const float*)d_in[3];
    const float* w2 = (const float*)d_in[4];
    float* out = (float*)d_out;

    cudaFuncSetAttribute(gemm1_kernel, cudaFuncAttributeMaxDynamicSharedMemorySize, SMEMSZ);
    cudaFuncSetAttribute(gemm2_kernel, cudaFuncAttributeMaxDynamicSharedMemorySize, SMEMSZ);

    __nv_bfloat16 *w1p, *w3p, *w2p, *xp;
    cudaGetSymbolAddress((void**)&w1p, g_w1);
    cudaGetSymbolAddress((void**)&w3p, g_w3);
    cudaGetSymbolAddress((void**)&w2p, g_w2);
    cudaGetSymbolAddress((void**)&xp,  g_x);

    zero_kernel<<<2048, 256>>>(out);
    router_kernel<<<TOKS, 256>>>(x, gw);
    offsets_kernel<<<1, 1>>>();
    split_kernel<<<4096, 256>>>(w1, w1p, w1p + SZW, SZW / 4);
    split_kernel<<<4096, 256>>>(w3, w3p, w3p + SZW, SZW / 4);
    split_kernel<<<4096, 256>>>(w2, w2p, w2p + SZW, SZW / 4);
    split_kernel<<<512,  256>>>(x,  xp,  xp + SZX,  SZX / 4);
    gemm1_kernel<<<dim3(TOKS / 256, ID / 64, NE), 512, SMEMSZ>>>();
    gemm2_kernel<<<dim3(TOKS / 256, HD / 128, NE), 512, SMEMSZ>>>(out);
}